// round 10
// baseline (speedup 1.0000x reference)
#include <cuda_runtime.h>
#include <math.h>
#include <stdint.h>

#define DDIM   64
#define KCODES 2048
#define NPTS   32768
#define HW     1024
#define PTS    128            // points per CTA
#define NB     256            // 8-code blocks
#define XSTR   136            // xs row stride
#define CAP    24
#define C1B    2.6e-3f        // dist-level ||x||*||e|| coeff (R5/R9-proven)
#define C2B    6.4e-4f        // esq coeff (R5/R9-proven)
#define ABSL   0.03f
#define FINF   3.402823e+38f

__device__ int    g_idx[NPTS];
__device__ float  g_esq[KCODES];
__device__ float  g_bf[NB * 32 * 20];   // tf32 B fragments (single pass)
__device__ float4 g_ep4[NB * 4];        // per (block,q): (Q0, A0, Q1, A1)

static __device__ __forceinline__ float to_tf32(float x) {
    float r; asm("cvt.rna.tf32.f32 %0, %1;" : "=f"(r) : "f"(x)); return r;
}
static __device__ __forceinline__ unsigned long long enc_key(float dist, int code) {
    unsigned int u = __float_as_uint(dist);
    u = (u & 0x80000000u) ? ~u : (u | 0x80000000u);
    return ((unsigned long long)u << 32) | (unsigned)code;
}
static __device__ __forceinline__ void mma8(float& c0, float& c1, float& c2, float& c3,
                                            float a0, float a1, float a2, float a3,
                                            float b0, float b1) {
    asm("mma.sync.aligned.m16n8k8.row.col.f32.tf32.tf32.f32 "
        "{%0,%1,%2,%3}, {%4,%5,%6,%7}, {%8,%9}, {%0,%1,%2,%3};"
        : "+f"(c0), "+f"(c1), "+f"(c2), "+f"(c3)
        : "r"(__float_as_uint(a0)), "r"(__float_as_uint(a1)),
          "r"(__float_as_uint(a2)), "r"(__float_as_uint(a3)),
          "r"(__float_as_uint(b0)), "r"(__float_as_uint(b1)));
}

// ---------------------------------------------------------------------------
// Prep 1: exact esq per code (proven sequential order)
// ---------------------------------------------------------------------------
__global__ void prep_epi(const float* __restrict__ cb) {
    int k = blockIdx.x * blockDim.x + threadIdx.x;
    if (k >= KCODES) return;
    const float4* r = reinterpret_cast<const float4*>(cb + (size_t)k * DDIM);
    float4 v[16];
    #pragma unroll
    for (int i = 0; i < 16; ++i) v[i] = __ldg(&r[i]);
    float s = 0.f;
    #pragma unroll
    for (int i = 0; i < 16; ++i) {
        s = fmaf(v[i].x, v[i].x, s); s = fmaf(v[i].y, v[i].y, s);
        s = fmaf(v[i].z, v[i].z, s); s = fmaf(v[i].w, v[i].w, s);
    }
    g_esq[k] = s;
}

// ---------------------------------------------------------------------------
// Prep 2: tf32 B fragments (dims 0..63 = tf32(e); 64: -h; 65: -l; 66..71: 0
// where h + l ~= esq/2) + epilogue coeffs (Q = C1B*||e||, A = C2B*esq + ABSL)
// ---------------------------------------------------------------------------
__global__ void prep_bf(const float* __restrict__ cb) {
    int t = blockIdx.x * blockDim.x + threadIdx.x;    // 0..8191
    if (t >= NB * 32) return;
    int lane = t & 31;
    int nb   = t >> 5;
    int g = lane >> 2, q = lane & 3;
    int code = nb * 8 + g;
    const float* e = cb + (size_t)code * DDIM;
    float esq = g_esq[code];
    float h = to_tf32(0.5f * esq);
    float l = to_tf32(0.5f * esq - h);

    float w[20];
    #pragma unroll
    for (int s = 0; s < 9; ++s) {
        int kA = s * 8 + q, kB = kA + 4;
        w[2 * s]     = (kA < 64) ? to_tf32(__ldg(&e[kA]))
                                 : (kA == 64 ? -h : (kA == 65 ? -l : 0.f));
        w[2 * s + 1] = (kB < 64) ? to_tf32(__ldg(&e[kB]))
                                 : (kB == 64 ? -h : (kB == 65 ? -l : 0.f));
    }
    w[18] = 0.f; w[19] = 0.f;
    float4* dst = reinterpret_cast<float4*>(g_bf + (size_t)t * 20);
    #pragma unroll
    for (int i = 0; i < 5; ++i)
        dst[i] = make_float4(w[4 * i], w[4 * i + 1], w[4 * i + 2], w[4 * i + 3]);

    if (g == 0) {   // one thread per (nb, q): coeffs for codes nb*8+2q, +1
        int c0 = nb * 8 + 2 * q, c1 = c0 + 1;
        float e0 = g_esq[c0], e1 = g_esq[c1];
        g_ep4[nb * 4 + q] = make_float4(C1B * sqrtf(e0), fmaf(C2B, e0, ABSL),
                                        C1B * sqrtf(e1), fmaf(C2B, e1, ABSL));
    }
}

// ---------------------------------------------------------------------------
// Main: single tf32 MMA pass, bound in epilogue, list push + exact recheck.
// 256 thr = 8 warps x m16 rows.
// ---------------------------------------------------------------------------
__global__ __launch_bounds__(256, 2)
void vq_tf32(const float* __restrict__ laten, const float* __restrict__ cb,
             float* __restrict__ out) {
    extern __shared__ char smraw[];
    float* xs   = reinterpret_cast<float*>(smraw);                  // 64*136
    float* sxsq = xs + DDIM * XSTR;                                  // 128
    float* sxn  = sxsq + PTS;                                        // 128
    float* sTf  = sxn + PTS;                                         // 128
    float* sL   = sTf + PTS;                                         // 128*CAP
    int*   sC   = reinterpret_cast<int*>(sL + PTS * CAP);            // 128*CAP
    int*   scnt = sC + PTS * CAP;                                    // 128
    int*   soflow = scnt + PTS;                                      // 128
    int*   socnt  = soflow + PTS;                                    // 1 (+pad)
    unsigned long long* skey =
        reinterpret_cast<unsigned long long*>(socnt + 2);            // 8B aligned

    const int tid  = threadIdx.x;
    const int lane = tid & 31;
    const int w    = tid >> 5;
    const int g = lane >> 2, q = lane & 3;
    const int r0 = w * 16 + g, r1 = r0 + 8;

    const int p0  = blockIdx.x * PTS;
    const int b   = p0 >> 10;
    const int hw0 = p0 & 1023;
    const float* lat_b = laten + (size_t)b * (DDIM * HW) + hw0;

    // stage x tile
    #pragma unroll
    for (int i = 0; i < 8; ++i) {
        int idx = tid + i * 256;
        int d = idx >> 5, p4 = idx & 31;
        float4 v = *reinterpret_cast<const float4*>(lat_b + d * HW + p4 * 4);
        *reinterpret_cast<float4*>(&xs[d * XSTR + p4 * 4]) = v;
    }
    if (tid < PTS) scnt[tid] = 0;
    if (tid == 0) *socnt = 0;
    __syncthreads();
    if (tid < PTS) {                            // exact xsq, sequential d
        float s = 0.f;
        #pragma unroll 8
        for (int d = 0; d < DDIM; ++d) {
            float v = xs[d * XSTR + tid];
            s = fmaf(v, v, s);
        }
        sxsq[tid] = s;
        sxn[tid]  = sqrtf(s);
    }
    __syncthreads();

    // A fragments (tf32)
    float a[9][4];
    #pragma unroll
    for (int s = 0; s < 9; ++s) {
        int kA = s * 8 + q, kB = kA + 4;
        float vA0, vA1, vB0, vB1;
        if (kA < 64) { vA0 = to_tf32(xs[kA * XSTR + r0]); vA1 = to_tf32(xs[kA * XSTR + r1]); }
        else if (kA < 66) { vA0 = 1.f; vA1 = 1.f; }          // dims 64,65
        else { vA0 = 0.f; vA1 = 0.f; }
        if (kB < 64) { vB0 = to_tf32(xs[kB * XSTR + r0]); vB1 = to_tf32(xs[kB * XSTR + r1]); }
        else if (kB < 66) { vB0 = 1.f; vB1 = 1.f; }
        else { vB0 = 0.f; vB1 = 0.f; }
        a[s][0] = vA0; a[s][1] = vA1; a[s][2] = vB0; a[s][3] = vB1;
    }
    const float xsq0 = sxsq[r0], xsq1 = sxsq[r1];
    const float xn0  = sxn[r0],  xn1  = sxn[r1];

    float T0 = FINF, T1 = FINF;

    const float* base = g_bf + (size_t)lane * 20;
    float4 bufA[5], bufB[5];
    #pragma unroll
    for (int i = 0; i < 5; ++i)
        bufA[i] = __ldg(reinterpret_cast<const float4*>(base) + i);

    #define EPILOGUE(C0, C1, C2, C3, EP, CODE0)                                   \
    do {                                                                          \
        float d00 = fmaf(-2.f, (C0), xsq0);                                       \
        float d01 = fmaf(-2.f, (C1), xsq0);                                       \
        float d10 = fmaf(-2.f, (C2), xsq1);                                       \
        float d11 = fmaf(-2.f, (C3), xsq1);                                       \
        float b00 = fmaf(xn0, (EP).x, (EP).y);                                    \
        float b01 = fmaf(xn0, (EP).z, (EP).w);                                    \
        float b10 = fmaf(xn1, (EP).x, (EP).y);                                    \
        float b11 = fmaf(xn1, (EP).z, (EP).w);                                    \
        T0 = fminf(T0, d00 + b00); T0 = fminf(T0, d01 + b01);                     \
        T1 = fminf(T1, d10 + b10); T1 = fminf(T1, d11 + b11);                     \
        float l00 = d00 - b00, l01 = d01 - b01;                                   \
        float l10 = d10 - b10, l11 = d11 - b11;                                   \
        if (l00 <= T0) { int i_ = atomicAdd(&scnt[r0], 1);                        \
            if (i_ < CAP) { sL[r0 * CAP + i_] = l00; sC[r0 * CAP + i_] = (CODE0); } } \
        if (l01 <= T0) { int i_ = atomicAdd(&scnt[r0], 1);                        \
            if (i_ < CAP) { sL[r0 * CAP + i_] = l01; sC[r0 * CAP + i_] = (CODE0) + 1; } } \
        if (l10 <= T1) { int i_ = atomicAdd(&scnt[r1], 1);                        \
            if (i_ < CAP) { sL[r1 * CAP + i_] = l10; sC[r1 * CAP + i_] = (CODE0); } } \
        if (l11 <= T1) { int i_ = atomicAdd(&scnt[r1], 1);                        \
            if (i_ < CAP) { sL[r1 * CAP + i_] = l11; sC[r1 * CAP + i_] = (CODE0) + 1; } } \
    } while (0)

    for (int nb = 0; nb < NB; nb += 2) {
        float4 epA = __ldg(&g_ep4[nb * 4 + q]);
        float4 epB = __ldg(&g_ep4[(nb + 1) * 4 + q]);
        #pragma unroll
        for (int i = 0; i < 5; ++i)
            bufB[i] = __ldg(reinterpret_cast<const float4*>(base + (size_t)(nb + 1) * 640) + i);
        {
            const float* wv = reinterpret_cast<const float*>(bufA);
            float c0 = 0.f, c1 = 0.f, c2 = 0.f, c3 = 0.f;
            #pragma unroll
            for (int s = 0; s < 9; ++s)
                mma8(c0, c1, c2, c3, a[s][0], a[s][1], a[s][2], a[s][3],
                     wv[2 * s], wv[2 * s + 1]);
            EPILOGUE(c0, c1, c2, c3, epA, nb * 8 + 2 * q);
        }
        if (nb + 2 < NB) {
            #pragma unroll
            for (int i = 0; i < 5; ++i)
                bufA[i] = __ldg(reinterpret_cast<const float4*>(base + (size_t)(nb + 2) * 640) + i);
        }
        {
            const float* wv = reinterpret_cast<const float*>(bufB);
            float c0 = 0.f, c1 = 0.f, c2 = 0.f, c3 = 0.f;
            #pragma unroll
            for (int s = 0; s < 9; ++s)
                mma8(c0, c1, c2, c3, a[s][0], a[s][1], a[s][2], a[s][3],
                     wv[2 * s], wv[2 * s + 1]);
            EPILOGUE(c0, c1, c2, c3, epB, (nb + 1) * 8 + 2 * q);
        }
        if ((nb & 14) == 14) {   // tighten T across q-lanes every 16 blocks
            T0 = fminf(T0, __shfl_xor_sync(0xFFFFFFFFu, T0, 1));
            T0 = fminf(T0, __shfl_xor_sync(0xFFFFFFFFu, T0, 2));
            T1 = fminf(T1, __shfl_xor_sync(0xFFFFFFFFu, T1, 1));
            T1 = fminf(T1, __shfl_xor_sync(0xFFFFFFFFu, T1, 2));
        }
    }
    #undef EPILOGUE

    // final point-level thresholds
    T0 = fminf(T0, __shfl_xor_sync(0xFFFFFFFFu, T0, 1));
    T0 = fminf(T0, __shfl_xor_sync(0xFFFFFFFFu, T0, 2));
    T1 = fminf(T1, __shfl_xor_sync(0xFFFFFFFFu, T1, 1));
    T1 = fminf(T1, __shfl_xor_sync(0xFFFFFFFFu, T1, 2));
    if (q == 0) { sTf[r0] = T0; sTf[r1] = T1; }
    __syncthreads();

    // exact recheck of surviving candidates (proven fp32 formula)
    if (tid < PTS) {
        int n = scnt[tid];
        if (n >= 1 && n <= CAP) {
            float xq = sxsq[tid];
            float Tf = sTf[tid];
            unsigned long long best = ~0ULL;
            for (int i = 0; i < n; ++i) {
                if (sL[tid * CAP + i] > Tf) continue;
                int code = sC[tid * CAP + i];
                const float* e = cb + (size_t)code * DDIM;
                float s = 0.f;
                #pragma unroll 8
                for (int d = 0; d < DDIM; ++d)
                    s = fmaf(xs[d * XSTR + tid], __ldg(&e[d]), s);
                unsigned long long kk = enc_key(fmaf(-2.f, s, xq) + g_esq[code], code);
                if (kk < best) best = kk;
            }
            int code = (int)(best & 0xFFFFFFFFULL);
            g_idx[p0 + tid] = code;
            out[p0 + tid]   = (float)code;
        } else {
            int i = atomicAdd(socnt, 1);
            soflow[i] = tid;
        }
    }
    __syncthreads();

    // cooperative exact fallback (overflow; prob ~0)
    const int nf = *socnt;
    for (int i = 0; i < nf; ++i) {
        int pl = soflow[i];
        if (tid == 0) *skey = ~0ULL;
        __syncthreads();
        float xq = sxsq[pl];
        unsigned long long mk = ~0ULL;
        for (int c = tid * 8; c < tid * 8 + 8; ++c) {
            const float* e = cb + (size_t)c * DDIM;
            float s = 0.f;
            #pragma unroll 8
            for (int d = 0; d < DDIM; ++d)
                s = fmaf(xs[d * XSTR + pl], __ldg(&e[d]), s);
            unsigned long long kk = enc_key(fmaf(-2.f, s, xq) + g_esq[c], c);
            if (kk < mk) mk = kk;
        }
        atomicMin(skey, mk);
        __syncthreads();
        if (tid == 0) {
            int code = (int)(*skey & 0xFFFFFFFFULL);
            g_idx[p0 + pl] = code;
            out[p0 + pl]   = (float)code;
        }
        __syncthreads();
    }
}

// ---------------------------------------------------------------------------
// Gather: coalesced stores, cached cb reads
// ---------------------------------------------------------------------------
__global__ __launch_bounds__(256)
void gather_kernel(const float* __restrict__ cb, float* __restrict__ out) {
    __shared__ int sidx[64];
    const int tid = threadIdx.x;
    const int b   = blockIdx.x >> 4;
    const int hw0 = (blockIdx.x & 15) * 64;
    if (tid < 64) sidx[tid] = g_idx[b * HW + hw0 + tid];
    __syncthreads();
    const int hw4   = tid & 15;
    const int dbase = tid >> 4;
    const int k0 = sidx[hw4 * 4], k1 = sidx[hw4 * 4 + 1];
    const int k2 = sidx[hw4 * 4 + 2], k3 = sidx[hw4 * 4 + 3];
    #pragma unroll
    for (int it = 0; it < 4; ++it) {
        int d = dbase + it * 16;
        float4 v;
        v.x = __ldg(&cb[k0 * DDIM + d]);
        v.y = __ldg(&cb[k1 * DDIM + d]);
        v.z = __ldg(&cb[k2 * DDIM + d]);
        v.w = __ldg(&cb[k3 * DDIM + d]);
        *reinterpret_cast<float4*>(
            &out[NPTS + (size_t)b * (DDIM * HW) + d * HW + hw0 + hw4 * 4]) = v;
    }
}

extern "C" void kernel_launch(void* const* d_in, const int* in_sizes, int n_in,
                              void* d_out, int out_size) {
    const float* laten = (const float*)d_in[0];   // (32, 64, 32, 32) f32
    const float* cb    = (const float*)d_in[1];   // (2048, 64) f32
    float* out = (float*)d_out;                   // [32768 idx | 2097152 quant]

    const int smem = (DDIM * XSTR + 3 * PTS + 2 * PTS * CAP + 2 * PTS + 4) * 4 + 16;
    cudaFuncSetAttribute(vq_tf32, cudaFuncAttributeMaxDynamicSharedMemorySize, smem);

    prep_epi<<<KCODES / 256, 256>>>(cb);
    prep_bf<<<(NB * 32) / 256, 256>>>(cb);
    vq_tf32<<<NPTS / PTS, 256, smem>>>(laten, cb, out);
    gather_kernel<<<(32 * HW) / 64, 256>>>(cb, out);
}

// round 11
// speedup vs baseline: 6.2289x; 6.2289x over previous
#include <cuda_runtime.h>
#include <math.h>
#include <stdint.h>

#define DDIM   64
#define KCODES 2048
#define NPTS   32768
#define HW     1024
#define PTS    128            // points per CTA
#define NB     256            // 8-code blocks total
#define NBU    64             // blocks screened in pass U (512 codes)
#define XSTR   136            // xs row stride
#define CAP    28
#define C1B    2.6e-3f        // dist-level ||x||*||e|| coeff (R5/R9-proven)
#define C2B    6.4e-4f        // esq coeff (R5/R9-proven)
#define ABSL   0.03f
#define FINF   3.402823e+38f

__device__ int    g_idx[NPTS];
__device__ float  g_esq[KCODES];
__device__ float  g_bf[NB * 32 * 20];   // tf32 B fragments (dist-aug only)
__device__ float4 g_ep4[NB * 4];        // per (block,q): (Q0, A0, Q1, A1)

static __device__ __forceinline__ float to_tf32(float x) {
    float r; asm("cvt.rna.tf32.f32 %0, %1;" : "=f"(r) : "f"(x)); return r;
}
static __device__ __forceinline__ unsigned long long enc_key(float dist, int code) {
    unsigned int u = __float_as_uint(dist);
    u = (u & 0x80000000u) ? ~u : (u | 0x80000000u);
    return ((unsigned long long)u << 32) | (unsigned)code;
}
static __device__ __forceinline__ void mma8(float& c0, float& c1, float& c2, float& c3,
                                            float a0, float a1, float a2, float a3,
                                            float b0, float b1) {
    asm("mma.sync.aligned.m16n8k8.row.col.f32.tf32.tf32.f32 "
        "{%0,%1,%2,%3}, {%4,%5,%6,%7}, {%8,%9}, {%0,%1,%2,%3};"
        : "+f"(c0), "+f"(c1), "+f"(c2), "+f"(c3)
        : "r"(__float_as_uint(a0)), "r"(__float_as_uint(a1)),
          "r"(__float_as_uint(a2)), "r"(__float_as_uint(a3)),
          "r"(__float_as_uint(b0)), "r"(__float_as_uint(b1)));
}

// ---------------------------------------------------------------------------
// Prep 1: exact esq per code (proven sequential order)
// ---------------------------------------------------------------------------
__global__ void prep_epi(const float* __restrict__ cb) {
    int k = blockIdx.x * blockDim.x + threadIdx.x;
    if (k >= KCODES) return;
    const float4* r = reinterpret_cast<const float4*>(cb + (size_t)k * DDIM);
    float4 v[16];
    #pragma unroll
    for (int i = 0; i < 16; ++i) v[i] = __ldg(&r[i]);
    float s = 0.f;
    #pragma unroll
    for (int i = 0; i < 16; ++i) {
        s = fmaf(v[i].x, v[i].x, s); s = fmaf(v[i].y, v[i].y, s);
        s = fmaf(v[i].z, v[i].z, s); s = fmaf(v[i].w, v[i].w, s);
    }
    g_esq[k] = s;
}

// ---------------------------------------------------------------------------
// Prep 2: tf32 B fragments (dims 0..63 = tf32(e); 64: -h; 65: -l; 66..71: 0;
// h + l ~= esq/2) + epilogue coeffs (Q = C1B*||e||, A = C2B*esq + ABSL)
// ---------------------------------------------------------------------------
__global__ void prep_bf(const float* __restrict__ cb) {
    int t = blockIdx.x * blockDim.x + threadIdx.x;    // 0..8191
    if (t >= NB * 32) return;
    int lane = t & 31;
    int nb   = t >> 5;
    int g = lane >> 2, q = lane & 3;
    int code = nb * 8 + g;
    const float* e = cb + (size_t)code * DDIM;
    float esq = g_esq[code];
    float h = to_tf32(0.5f * esq);
    float l = to_tf32(0.5f * esq - h);

    float w[20];
    #pragma unroll
    for (int s = 0; s < 9; ++s) {
        int kA = s * 8 + q, kB = kA + 4;
        w[2 * s]     = (kA < 64) ? to_tf32(__ldg(&e[kA]))
                                 : (kA == 64 ? -h : (kA == 65 ? -l : 0.f));
        w[2 * s + 1] = (kB < 64) ? to_tf32(__ldg(&e[kB]))
                                 : (kB == 64 ? -h : (kB == 65 ? -l : 0.f));
    }
    w[18] = 0.f; w[19] = 0.f;
    float4* dst = reinterpret_cast<float4*>(g_bf + (size_t)t * 20);
    #pragma unroll
    for (int i = 0; i < 5; ++i)
        dst[i] = make_float4(w[4 * i], w[4 * i + 1], w[4 * i + 2], w[4 * i + 3]);

    if (g == 0) {   // one thread per (nb, q): coeffs for codes nb*8+2q, +1
        int c0 = nb * 8 + 2 * q, c1 = c0 + 1;
        float e0 = g_esq[c0], e1 = g_esq[c1];
        g_ep4[nb * 4 + q] = make_float4(C1B * sqrtf(e0), fmaf(C2B, e0, ABSL),
                                        C1B * sqrtf(e1), fmaf(C2B, e1, ABSL));
    }
}

// ---------------------------------------------------------------------------
// Main: pass U over NBU blocks (subset threshold T), pass L over all blocks
// with FINAL T (rare pushes), exact recheck. 256 thr = 8 warps x m16 rows.
// ---------------------------------------------------------------------------
__global__ __launch_bounds__(256, 2)
void vq_tf32(const float* __restrict__ laten, const float* __restrict__ cb,
             float* __restrict__ out) {
    extern __shared__ char smraw[];
    float* xs     = reinterpret_cast<float*>(smraw);        // 64*136
    float* sxsq   = xs + DDIM * XSTR;                       // 128
    float* sxn    = sxsq + PTS;                             // 128
    int*   sC     = reinterpret_cast<int*>(sxn + PTS);      // 128*CAP
    int*   scnt   = sC + PTS * CAP;                         // 128
    int*   soflow = scnt + PTS;                             // 128
    int*   socnt  = soflow + PTS;                           // 1 (+pad)
    unsigned long long* skey =
        reinterpret_cast<unsigned long long*>(socnt + 2);   // 8B aligned

    const int tid  = threadIdx.x;
    const int lane = tid & 31;
    const int w    = tid >> 5;
    const int g = lane >> 2, q = lane & 3;
    const int r0 = w * 16 + g, r1 = r0 + 8;

    const int p0  = blockIdx.x * PTS;
    const int b   = p0 >> 10;
    const int hw0 = p0 & 1023;
    const float* lat_b = laten + (size_t)b * (DDIM * HW) + hw0;

    // stage x tile
    #pragma unroll
    for (int i = 0; i < 8; ++i) {
        int idx = tid + i * 256;
        int d = idx >> 5, p4 = idx & 31;
        float4 v = *reinterpret_cast<const float4*>(lat_b + d * HW + p4 * 4);
        *reinterpret_cast<float4*>(&xs[d * XSTR + p4 * 4]) = v;
    }
    if (tid < PTS) scnt[tid] = 0;
    if (tid == 0) *socnt = 0;
    __syncthreads();
    if (tid < PTS) {                            // exact xsq, sequential d
        float s = 0.f;
        #pragma unroll 8
        for (int d = 0; d < DDIM; ++d) {
            float v = xs[d * XSTR + tid];
            s = fmaf(v, v, s);
        }
        sxsq[tid] = s;
        sxn[tid]  = sqrtf(s);
    }
    __syncthreads();

    // A fragments (tf32)
    float a[9][4];
    #pragma unroll
    for (int s = 0; s < 9; ++s) {
        int kA = s * 8 + q, kB = kA + 4;
        float vA0, vA1, vB0, vB1;
        if (kA < 64) { vA0 = to_tf32(xs[kA * XSTR + r0]); vA1 = to_tf32(xs[kA * XSTR + r1]); }
        else if (kA < 66) { vA0 = 1.f; vA1 = 1.f; }          // dims 64,65
        else { vA0 = 0.f; vA1 = 0.f; }
        if (kB < 64) { vB0 = to_tf32(xs[kB * XSTR + r0]); vB1 = to_tf32(xs[kB * XSTR + r1]); }
        else if (kB < 66) { vB0 = 1.f; vB1 = 1.f; }
        else { vB0 = 0.f; vB1 = 0.f; }
        a[s][0] = vA0; a[s][1] = vA1; a[s][2] = vB0; a[s][3] = vB1;
    }
    const float xsq0 = sxsq[r0], xsq1 = sxsq[r1];
    const float xn0  = sxn[r0],  xn1  = sxn[r1];

    const float* base = g_bf + (size_t)lane * 20;
    float4 bufA[5], bufB[5];
    float T0 = FINF, T1 = FINF;

    // ---- Pass U: subset threshold over blocks 0..NBU-1 ----
    #pragma unroll
    for (int i = 0; i < 5; ++i)
        bufA[i] = __ldg(reinterpret_cast<const float4*>(base) + i);
    for (int nb = 0; nb < NBU; nb += 2) {
        float4 epA = __ldg(&g_ep4[nb * 4 + q]);
        float4 epB = __ldg(&g_ep4[(nb + 1) * 4 + q]);
        #pragma unroll
        for (int i = 0; i < 5; ++i)
            bufB[i] = __ldg(reinterpret_cast<const float4*>(base + (size_t)(nb + 1) * 640) + i);
        {
            const float* wv = reinterpret_cast<const float*>(bufA);
            float c0 = 0.f, c1 = 0.f, c2 = 0.f, c3 = 0.f;
            #pragma unroll
            for (int s = 0; s < 9; ++s)
                mma8(c0, c1, c2, c3, a[s][0], a[s][1], a[s][2], a[s][3],
                     wv[2 * s], wv[2 * s + 1]);
            T0 = fminf(T0, fmaf(-2.f, c0, xsq0) + fmaf(xn0, epA.x, epA.y));
            T0 = fminf(T0, fmaf(-2.f, c1, xsq0) + fmaf(xn0, epA.z, epA.w));
            T1 = fminf(T1, fmaf(-2.f, c2, xsq1) + fmaf(xn1, epA.x, epA.y));
            T1 = fminf(T1, fmaf(-2.f, c3, xsq1) + fmaf(xn1, epA.z, epA.w));
        }
        if (nb + 2 < NBU) {
            #pragma unroll
            for (int i = 0; i < 5; ++i)
                bufA[i] = __ldg(reinterpret_cast<const float4*>(base + (size_t)(nb + 2) * 640) + i);
        }
        {
            const float* wv = reinterpret_cast<const float*>(bufB);
            float c0 = 0.f, c1 = 0.f, c2 = 0.f, c3 = 0.f;
            #pragma unroll
            for (int s = 0; s < 9; ++s)
                mma8(c0, c1, c2, c3, a[s][0], a[s][1], a[s][2], a[s][3],
                     wv[2 * s], wv[2 * s + 1]);
            T0 = fminf(T0, fmaf(-2.f, c0, xsq0) + fmaf(xn0, epB.x, epB.y));
            T0 = fminf(T0, fmaf(-2.f, c1, xsq0) + fmaf(xn0, epB.z, epB.w));
            T1 = fminf(T1, fmaf(-2.f, c2, xsq1) + fmaf(xn1, epB.x, epB.y));
            T1 = fminf(T1, fmaf(-2.f, c3, xsq1) + fmaf(xn1, epB.z, epB.w));
        }
    }
    // finalize T per point (valid global upper bound: subset min of U)
    T0 = fminf(T0, __shfl_xor_sync(0xFFFFFFFFu, T0, 1));
    T0 = fminf(T0, __shfl_xor_sync(0xFFFFFFFFu, T0, 2));
    T1 = fminf(T1, __shfl_xor_sync(0xFFFFFFFFu, T1, 1));
    T1 = fminf(T1, __shfl_xor_sync(0xFFFFFFFFu, T1, 2));

    // ---- Pass L: all blocks, FINAL T, rare pushes ----
    #pragma unroll
    for (int i = 0; i < 5; ++i)
        bufA[i] = __ldg(reinterpret_cast<const float4*>(base) + i);
    for (int nb = 0; nb < NB; nb += 2) {
        float4 epA = __ldg(&g_ep4[nb * 4 + q]);
        float4 epB = __ldg(&g_ep4[(nb + 1) * 4 + q]);
        #pragma unroll
        for (int i = 0; i < 5; ++i)
            bufB[i] = __ldg(reinterpret_cast<const float4*>(base + (size_t)(nb + 1) * 640) + i);
        {
            const float* wv = reinterpret_cast<const float*>(bufA);
            float c0 = 0.f, c1 = 0.f, c2 = 0.f, c3 = 0.f;
            #pragma unroll
            for (int s = 0; s < 9; ++s)
                mma8(c0, c1, c2, c3, a[s][0], a[s][1], a[s][2], a[s][3],
                     wv[2 * s], wv[2 * s + 1]);
            int code0 = nb * 8 + 2 * q;
            float l00 = fmaf(-2.f, c0, xsq0) - fmaf(xn0, epA.x, epA.y);
            float l01 = fmaf(-2.f, c1, xsq0) - fmaf(xn0, epA.z, epA.w);
            float l10 = fmaf(-2.f, c2, xsq1) - fmaf(xn1, epA.x, epA.y);
            float l11 = fmaf(-2.f, c3, xsq1) - fmaf(xn1, epA.z, epA.w);
            if (l00 <= T0) { int i_ = atomicAdd(&scnt[r0], 1); if (i_ < CAP) sC[r0 * CAP + i_] = code0; }
            if (l01 <= T0) { int i_ = atomicAdd(&scnt[r0], 1); if (i_ < CAP) sC[r0 * CAP + i_] = code0 + 1; }
            if (l10 <= T1) { int i_ = atomicAdd(&scnt[r1], 1); if (i_ < CAP) sC[r1 * CAP + i_] = code0; }
            if (l11 <= T1) { int i_ = atomicAdd(&scnt[r1], 1); if (i_ < CAP) sC[r1 * CAP + i_] = code0 + 1; }
        }
        if (nb + 2 < NB) {
            #pragma unroll
            for (int i = 0; i < 5; ++i)
                bufA[i] = __ldg(reinterpret_cast<const float4*>(base + (size_t)(nb + 2) * 640) + i);
        }
        {
            const float* wv = reinterpret_cast<const float*>(bufB);
            float c0 = 0.f, c1 = 0.f, c2 = 0.f, c3 = 0.f;
            #pragma unroll
            for (int s = 0; s < 9; ++s)
                mma8(c0, c1, c2, c3, a[s][0], a[s][1], a[s][2], a[s][3],
                     wv[2 * s], wv[2 * s + 1]);
            int code0 = (nb + 1) * 8 + 2 * q;
            float l00 = fmaf(-2.f, c0, xsq0) - fmaf(xn0, epB.x, epB.y);
            float l01 = fmaf(-2.f, c1, xsq0) - fmaf(xn0, epB.z, epB.w);
            float l10 = fmaf(-2.f, c2, xsq1) - fmaf(xn1, epB.x, epB.y);
            float l11 = fmaf(-2.f, c3, xsq1) - fmaf(xn1, epB.z, epB.w);
            if (l00 <= T0) { int i_ = atomicAdd(&scnt[r0], 1); if (i_ < CAP) sC[r0 * CAP + i_] = code0; }
            if (l01 <= T0) { int i_ = atomicAdd(&scnt[r0], 1); if (i_ < CAP) sC[r0 * CAP + i_] = code0 + 1; }
            if (l10 <= T1) { int i_ = atomicAdd(&scnt[r1], 1); if (i_ < CAP) sC[r1 * CAP + i_] = code0; }
            if (l11 <= T1) { int i_ = atomicAdd(&scnt[r1], 1); if (i_ < CAP) sC[r1 * CAP + i_] = code0 + 1; }
        }
    }
    __syncthreads();

    // ---- exact recheck (proven fp32 formula) ----
    if (tid < PTS) {
        int n = scnt[tid];
        if (n >= 1 && n <= CAP) {
            float xq = sxsq[tid];
            unsigned long long best = ~0ULL;
            for (int i = 0; i < n; ++i) {
                int code = sC[tid * CAP + i];
                const float* e = cb + (size_t)code * DDIM;
                float s = 0.f;
                #pragma unroll 8
                for (int d = 0; d < DDIM; ++d)
                    s = fmaf(xs[d * XSTR + tid], __ldg(&e[d]), s);
                unsigned long long kk = enc_key(fmaf(-2.f, s, xq) + g_esq[code], code);
                if (kk < best) best = kk;
            }
            int code = (int)(best & 0xFFFFFFFFULL);
            g_idx[p0 + tid] = code;
            out[p0 + tid]   = (float)code;
        } else {
            int i = atomicAdd(socnt, 1);
            soflow[i] = tid;
        }
    }
    __syncthreads();

    // ---- cooperative exact fallback (overflow; rare) ----
    const int nf = *socnt;
    for (int i = 0; i < nf; ++i) {
        int pl = soflow[i];
        if (tid == 0) *skey = ~0ULL;
        __syncthreads();
        float xq = sxsq[pl];
        unsigned long long mk = ~0ULL;
        for (int c = tid * 8; c < tid * 8 + 8; ++c) {
            const float* e = cb + (size_t)c * DDIM;
            float s = 0.f;
            #pragma unroll 8
            for (int d = 0; d < DDIM; ++d)
                s = fmaf(xs[d * XSTR + pl], __ldg(&e[d]), s);
            unsigned long long kk = enc_key(fmaf(-2.f, s, xq) + g_esq[c], c);
            if (kk < mk) mk = kk;
        }
        atomicMin(skey, mk);
        __syncthreads();
        if (tid == 0) {
            int code = (int)(*skey & 0xFFFFFFFFULL);
            g_idx[p0 + pl] = code;
            out[p0 + pl]   = (float)code;
        }
        __syncthreads();
    }
}

// ---------------------------------------------------------------------------
// Gather: coalesced stores, cached cb reads
// ---------------------------------------------------------------------------
__global__ __launch_bounds__(256)
void gather_kernel(const float* __restrict__ cb, float* __restrict__ out) {
    __shared__ int sidx[64];
    const int tid = threadIdx.x;
    const int b   = blockIdx.x >> 4;
    const int hw0 = (blockIdx.x & 15) * 64;
    if (tid < 64) sidx[tid] = g_idx[b * HW + hw0 + tid];
    __syncthreads();
    const int hw4   = tid & 15;
    const int dbase = tid >> 4;
    const int k0 = sidx[hw4 * 4], k1 = sidx[hw4 * 4 + 1];
    const int k2 = sidx[hw4 * 4 + 2], k3 = sidx[hw4 * 4 + 3];
    #pragma unroll
    for (int it = 0; it < 4; ++it) {
        int d = dbase + it * 16;
        float4 v;
        v.x = __ldg(&cb[k0 * DDIM + d]);
        v.y = __ldg(&cb[k1 * DDIM + d]);
        v.z = __ldg(&cb[k2 * DDIM + d]);
        v.w = __ldg(&cb[k3 * DDIM + d]);
        *reinterpret_cast<float4*>(
            &out[NPTS + (size_t)b * (DDIM * HW) + d * HW + hw0 + hw4 * 4]) = v;
    }
}

extern "C" void kernel_launch(void* const* d_in, const int* in_sizes, int n_in,
                              void* d_out, int out_size) {
    const float* laten = (const float*)d_in[0];   // (32, 64, 32, 32) f32
    const float* cb    = (const float*)d_in[1];   // (2048, 64) f32
    float* out = (float*)d_out;                   // [32768 idx | 2097152 quant]

    const int smem = (DDIM * XSTR + 2 * PTS + PTS * CAP + 2 * PTS + 4) * 4 + 16;
    cudaFuncSetAttribute(vq_tf32, cudaFuncAttributeMaxDynamicSharedMemorySize, smem);

    prep_epi<<<KCODES / 256, 256>>>(cb);
    prep_bf<<<(NB * 32) / 256, 256>>>(cb);
    vq_tf32<<<NPTS / PTS, 256, smem>>>(laten, cb, out);
    gather_kernel<<<(32 * HW) / 64, 256>>>(cb, out);
}